// round 7
// baseline (speedup 1.0000x reference)
#include <cuda_runtime.h>
#include <cuda_fp16.h>
#include <cstdint>

#define NDOM 4
#define NB   8192
#define NF   128
#define BM   128
#define NTILE 64
#define NPAIRS 2080            /* NTILE*(NTILE+1)/2 */
#define CHUNK 4
#define NCTA_X (NPAIRS / CHUNK) /* 520 */
#define NTHREADS 512
#define MARGIN 2e-4f
#define MAXFLAGS 1024

// ---------------- SMEM layout (byte offsets) ----------------
#define OFF_AH  0u             /* A hi 32KB (swizzled row-major fp16) */
#define OFF_AL  32768u
#define OFF_B   65536u         /* buf b at OFF_B + b*65536: hi 32KB, lo +32768 */
#define OFF_SCR 196608u        /* 128*4*8 floats = 16KB */
#define SMEM_BYTES 212992u

__device__ int g_labels[NDOM * NB];
__device__ int g_flag_cnt;
__device__ int g_flags[MAXFLAGS];
__device__ unsigned long long g_best[MAXFLAGS];
__device__ __half g_hi[NDOM * NB * NF];
__device__ __half g_lo[NDOM * NB * NF];
// per-row partial top-2: [d*NB+row][slot 0..63][8 floats: p1,p2,i1,n1,n2,j1,pad,pad]
__device__ float g_part[(size_t)NDOM * NB * 64 * 8];

// ---------------- helpers ----------------
__device__ __forceinline__ uint32_t smem_u32(const void* p) {
    uint32_t a;
    asm("{ .reg .u64 t; cvta.to.shared.u64 t, %1; cvt.u32.u64 %0, t; }"
        : "=r"(a) : "l"(p));
    return a;
}
__device__ __forceinline__ uint32_t fkey(float v) {
    uint32_t u = __float_as_uint(v);
    return (u & 0x80000000u) ? ~u : (u | 0x80000000u);
}
__device__ __forceinline__ void ldsm4(uint32_t* r, uint32_t addr) {
    asm volatile("ldmatrix.sync.aligned.m8n8.x4.shared.b16 {%0,%1,%2,%3}, [%4];"
                 : "=r"(r[0]), "=r"(r[1]), "=r"(r[2]), "=r"(r[3]) : "r"(addr));
}
__device__ __forceinline__ void mma16816(float* d, const uint32_t* a,
                                         const uint32_t* b) {
    asm volatile(
        "mma.sync.aligned.m16n8k16.row.col.f32.f16.f16.f32 "
        "{%0,%1,%2,%3}, {%4,%5,%6,%7}, {%8,%9}, {%0,%1,%2,%3};"
        : "+f"(d[0]), "+f"(d[1]), "+f"(d[2]), "+f"(d[3])
        : "r"(a[0]), "r"(a[1]), "r"(a[2]), "r"(a[3]), "r"(b[0]), "r"(b[1]));
}
#define CP_ASYNC(dst, src) \
    asm volatile("cp.async.cg.shared.global [%0], [%1], 16;" :: "r"(dst), "l"(src))
#define CP_COMMIT() asm volatile("cp.async.commit_group;" ::: "memory")
#define CP_WAIT1()  asm volatile("cp.async.wait_group 1;" ::: "memory")
#define CP_WAIT0()  asm volatile("cp.async.wait_group 0;" ::: "memory")

// Copy one 128x128 fp16 tile (hi+lo) gmem -> swizzled smem via cp.async.
__device__ __forceinline__ void copy_tile_async(
    uint32_t smem_hi, uint32_t smem_lo,
    const __half* __restrict__ gh, const __half* __restrict__ gl, int tid) {
#pragma unroll
    for (int it = 0; it < 8; ++it) {
        const int comp = it >> 2;
        const int rem = (it & 3) * NTHREADS + tid;   // 0..2047
        const int row = rem >> 4;
        const int kc = rem & 15;
        const uint32_t dstb = (uint32_t)row * 256u
            + (((uint32_t)kc * 16u) ^ (((uint32_t)row & 7u) << 4));
        const __half* src = (comp ? gl : gh) + row * NF + kc * 8;
        CP_ASYNC((comp ? smem_lo : smem_hi) + dstb, src);
    }
}

// top-2 merge primitive: fold candidate (q1,q2,qi) into (P1,P2,I1) (min side)
#define MERGE_MIN(P1, P2, I1, q1, q2, qi) \
    do { if ((q1) < (P1)) { P2 = fminf(P1, q2); P1 = q1; I1 = qi; } \
         else { P2 = fminf(P2, q1); } } while (0)
#define MERGE_MAX(N1, N2, J1, m1, m2, mi) \
    do { if ((m1) > (N1)) { N2 = fmaxf(N1, m2); N1 = m1; J1 = mi; } \
         else { N2 = fmaxf(N2, m1); } } while (0)

// ---------------- one-shot fp32 -> fp16 hi/lo split ----------------
__global__ void split_kernel(const float* __restrict__ emb) {
    const int i = blockIdx.x * blockDim.x + threadIdx.x;
    const float4 v = reinterpret_cast<const float4*>(emb)[i];
    const __half hx = __float2half_rn(v.x), hy = __float2half_rn(v.y);
    const __half hz = __float2half_rn(v.z), hw = __float2half_rn(v.w);
    const __half lx = __float2half_rn(v.x - __half2float(hx));
    const __half ly = __float2half_rn(v.y - __half2float(hy));
    const __half lz = __float2half_rn(v.z - __half2float(hz));
    const __half lw = __float2half_rn(v.w - __half2float(hw));
    uint2 hv, lv;
    hv.x = ((uint32_t)__half_as_ushort(hx)) | ((uint32_t)__half_as_ushort(hy) << 16);
    hv.y = ((uint32_t)__half_as_ushort(hz)) | ((uint32_t)__half_as_ushort(hw) << 16);
    lv.x = ((uint32_t)__half_as_ushort(lx)) | ((uint32_t)__half_as_ushort(ly) << 16);
    lv.y = ((uint32_t)__half_as_ushort(lz)) | ((uint32_t)__half_as_ushort(lw) << 16);
    reinterpret_cast<uint2*>(g_hi)[i] = hv;
    reinterpret_cast<uint2*>(g_lo)[i] = lv;
}

// ---------------- label normalization + flag reset ----------------
__global__ void convert_labels_kernel(const unsigned int* __restrict__ w, int n) {
    __shared__ int s_any;
    if (threadIdx.x == 0) { s_any = 0; g_flag_cnt = 0; }
    __syncthreads();
    int any = 0;
    for (int i = threadIdx.x; i < n / 2; i += blockDim.x)
        any |= (w[2 * i + 1] != 0u);
    if (any) atomicOr(&s_any, 1);
    for (int i = threadIdx.x; i < MAXFLAGS; i += blockDim.x) g_best[i] = 0ull;
    __syncthreads();
    const bool is64 = (s_any == 0);
    for (int i = threadIdx.x; i < n; i += blockDim.x)
        g_labels[i] = is64 ? (int)w[2 * i] : (int)w[i];
}

// ---------------- symmetric fused HMMA GEMM + two-sided mining ----------------
__global__ __launch_bounds__(NTHREADS, 1)
void mine_kernel() {
    extern __shared__ char smem[];
    const uint32_t sb = smem_u32(smem);
    const int tid = threadIdx.x;
    const int w = tid >> 5, L = tid & 31;
    const int wm = w & 3, wn = w >> 2;
    const int d = blockIdx.y;

    // decode CHUNK consecutive (it, jt>=it) pairs
    int itq[CHUNK], jtq[CHUNK];
    {
        int it = 0, pp = blockIdx.x * CHUNK;
        while (pp >= NTILE - it) { pp -= NTILE - it; ++it; }
        int jt = it + pp;
#pragma unroll
        for (int q = 0; q < CHUNK; ++q) {
            itq[q] = it; jtq[q] = jt;
            if (++jt == NTILE) { ++it; jt = it; }
        }
    }

    const __half* __restrict__ gh = g_hi + (size_t)d * NB * NF;
    const __half* __restrict__ gl = g_lo + (size_t)d * NB * NF;
    const int* __restrict__ labd = g_labels + d * NB;

    // prologue: A(it0) + B(jt0)
    copy_tile_async(sb + OFF_AH, sb + OFF_AL,
                    gh + (size_t)itq[0] * BM * NF, gl + (size_t)itq[0] * BM * NF, tid);
    copy_tile_async(sb + OFF_B, sb + OFF_B + 32768u,
                    gh + (size_t)jtq[0] * BM * NF, gl + (size_t)jtq[0] * BM * NF, tid);
    CP_COMMIT();

    const uint32_t cxA = ((uint32_t)(L >> 4) * 16u) ^ (((uint32_t)L & 7u) << 4);
    const uint32_t cxB = ((uint32_t)((L >> 3) & 1) * 16u) ^ (((uint32_t)L & 7u) << 4);
    uint32_t aBase[2];
#pragma unroll
    for (int mt = 0; mt < 2; ++mt) {
        const int rowA = wm * 32 + mt * 16 + (L & 7) + ((L >> 3) & 1) * 8;
        aBase[mt] = sb + OFF_AH + (uint32_t)rowA * 256u;
    }
    uint32_t bRow[2];
#pragma unroll
    for (int bi = 0; bi < 2; ++bi) {
        const int rowB = wn * 32 + bi * 16 + (L & 7) + (L >> 4) * 8;
        bRow[bi] = (uint32_t)rowB * 256u;
    }

    const int rbase = wm * 32 + (L >> 2);
    int li[4];
#pragma unroll
    for (int s = 0; s < 4; ++s)
        li[s] = labd[itq[0] * BM + rbase + (s & 1) * 8 + (s >> 1) * 16];

    const float INF = __int_as_float(0x7f800000);
    float* scr = reinterpret_cast<float*>(smem + OFF_SCR);

    for (int q = 0; q < CHUNK; ++q) {
        const int it = itq[q], jt = jtq[q];
        const bool diag = (it == jt);

        if (q + 1 < CHUNK && itq[q + 1] == it) {
            const uint32_t bo = OFF_B + (uint32_t)((q + 1) & 1) * 65536u;
            copy_tile_async(sb + bo, sb + bo + 32768u,
                            gh + (size_t)jtq[q + 1] * BM * NF,
                            gl + (size_t)jtq[q + 1] * BM * NF, tid);
            CP_COMMIT();
            CP_WAIT1();
        } else {
            CP_WAIT0();
        }
        __syncthreads();

        // column labels
        const int cb = jt * BM + wn * 32 + (L & 3) * 2;
        int labc[4][2];
#pragma unroll
        for (int nt = 0; nt < 4; ++nt) {
            const int2 lv = *reinterpret_cast<const int2*>(labd + cb + nt * 8);
            labc[nt][0] = lv.x; labc[nt][1] = lv.y;
        }

        // ---- MMA (3-pass fp16 hi/lo) ----
        float acc[2][4][4];
#pragma unroll
        for (int mt = 0; mt < 2; ++mt)
#pragma unroll
            for (int nt = 0; nt < 4; ++nt)
#pragma unroll
                for (int r = 0; r < 4; ++r) acc[mt][nt][r] = 0.0f;

        const uint32_t sbB = sb + OFF_B + (uint32_t)(q & 1) * 65536u;
#pragma unroll
        for (int ks = 0; ks < 8; ++ks) {
            const uint32_t offA = ((uint32_t)ks * 32u) ^ cxA;
            const uint32_t offB = ((uint32_t)ks * 32u) ^ cxB;
            uint32_t Ah[2][4], Al[2][4], Bh[2][4], Bl[2][4];
            ldsm4(Ah[0], aBase[0] + offA);
            ldsm4(Ah[1], aBase[1] + offA);
            ldsm4(Bh[0], sbB + bRow[0] + offB);
            ldsm4(Bh[1], sbB + bRow[1] + offB);
            ldsm4(Al[0], aBase[0] + 32768u + offA);
            ldsm4(Al[1], aBase[1] + 32768u + offA);
            ldsm4(Bl[0], sbB + 32768u + bRow[0] + offB);
            ldsm4(Bl[1], sbB + 32768u + bRow[1] + offB);
#pragma unroll
            for (int bi = 0; bi < 2; ++bi)
#pragma unroll
                for (int mt = 0; mt < 2; ++mt) {
                    mma16816(acc[mt][2 * bi],     Ah[mt], Bh[bi]);
                    mma16816(acc[mt][2 * bi + 1], Ah[mt], Bh[bi] + 2);
                }
#pragma unroll
            for (int bi = 0; bi < 2; ++bi)
#pragma unroll
                for (int mt = 0; mt < 2; ++mt) {
                    mma16816(acc[mt][2 * bi],     Al[mt], Bh[bi]);
                    mma16816(acc[mt][2 * bi + 1], Al[mt], Bh[bi] + 2);
                }
#pragma unroll
            for (int bi = 0; bi < 2; ++bi)
#pragma unroll
                for (int mt = 0; mt < 2; ++mt) {
                    mma16816(acc[mt][2 * bi],     Ah[mt], Bl[bi]);
                    mma16816(acc[mt][2 * bi + 1], Ah[mt], Bl[bi] + 2);
                }
        }

        // ---- row-side mining (rows of it over this tile's 128 cols) ----
        {
            float p1[4], p2[4], n1[4], n2[4];
            int i1[4], j1[4];
#pragma unroll
            for (int s = 0; s < 4; ++s) {
                p1[s] = INF; p2[s] = INF; n1[s] = -INF; n2[s] = -INF;
                i1[s] = -1; j1[s] = -1;
            }
#pragma unroll
            for (int nt = 0; nt < 4; ++nt)
#pragma unroll
                for (int e = 0; e < 2; ++e) {
                    const int lj = labc[nt][e];
                    const int j = cb + nt * 8 + e;   // domain-local col index
#pragma unroll
                    for (int s = 0; s < 4; ++s) {
                        const float v = acc[s >> 1][nt][(s & 1) * 2 + e];
                        if (lj == li[s]) {
                            const int growl = it * BM + rbase + (s & 1) * 8 + (s >> 1) * 16;
                            if (j != growl) {
                                if (v < p1[s]) { p2[s] = p1[s]; p1[s] = v; i1[s] = j; }
                                else if (v < p2[s]) p2[s] = v;
                            }
                        } else {
                            if (v > n1[s]) { n2[s] = n1[s]; n1[s] = v; j1[s] = j; }
                            else if (v > n2[s]) n2[s] = v;
                        }
                    }
                }
            // reduce across 4 lanes sharing each row (xor 1,2)
#pragma unroll
            for (int s = 0; s < 4; ++s) {
#pragma unroll
                for (int off = 1; off <= 2; off <<= 1) {
                    const float q1 = __shfl_xor_sync(~0u, p1[s], off);
                    const float q2 = __shfl_xor_sync(~0u, p2[s], off);
                    const int   qi = __shfl_xor_sync(~0u, i1[s], off);
                    const float m1 = __shfl_xor_sync(~0u, n1[s], off);
                    const float m2 = __shfl_xor_sync(~0u, n2[s], off);
                    const int   mi = __shfl_xor_sync(~0u, j1[s], off);
                    MERGE_MIN(p1[s], p2[s], i1[s], q1, q2, qi);
                    MERGE_MAX(n1[s], n2[s], j1[s], m1, m2, mi);
                }
            }
            if ((L & 3) == 0) {
#pragma unroll
                for (int s = 0; s < 4; ++s) {
                    const int row = rbase + (s & 1) * 8 + (s >> 1) * 16;
                    float* sr = scr + (row * 4 + wn) * 8;
                    sr[0] = p1[s]; sr[1] = p2[s];
                    reinterpret_cast<int*>(sr)[2] = i1[s];
                    sr[3] = n1[s]; sr[4] = n2[s];
                    reinterpret_cast<int*>(sr)[5] = j1[s];
                }
            }
        }
        __syncthreads();
        if (tid < 128) {
            const int row = tid;
            const float* s0 = scr + (row * 4) * 8;
            float P1 = s0[0], P2 = s0[1], N1 = s0[3], N2 = s0[4];
            int I1 = reinterpret_cast<const int*>(s0)[2];
            int J1 = reinterpret_cast<const int*>(s0)[5];
#pragma unroll
            for (int o = 1; o < 4; ++o) {
                const float* sr = scr + (row * 4 + o) * 8;
                MERGE_MIN(P1, P2, I1, sr[0], sr[1], reinterpret_cast<const int*>(sr)[2]);
                MERGE_MAX(N1, N2, J1, sr[3], sr[4], reinterpret_cast<const int*>(sr)[5]);
            }
            float4* dst = reinterpret_cast<float4*>(
                g_part + ((size_t)(d * NB + it * BM + row) * 64 + jt) * 8);
            dst[0] = make_float4(P1, P2, __int_as_float(I1), N1);
            dst[1] = make_float4(N2, __int_as_float(J1), 0.f, 0.f);
        }
        __syncthreads();

        // ---- column-side mining (rows of jt via symmetry), skip diagonal ----
        if (!diag) {
#pragma unroll
            for (int c = 0; c < 8; ++c) {
                const int nt = c >> 1, e = c & 1;
                const int lj = labc[nt][e];
                float P1 = INF, P2 = INF, N1 = -INF, N2 = -INF;
                int I1 = -1, J1 = -1;
#pragma unroll
                for (int s = 0; s < 4; ++s) {
                    const float v = acc[s >> 1][nt][(s & 1) * 2 + e];
                    const int i = it * BM + rbase + (s & 1) * 8 + (s >> 1) * 16;
                    if (li[s] == lj) {
                        if (v < P1) { P2 = P1; P1 = v; I1 = i; }
                        else if (v < P2) P2 = v;
                    } else {
                        if (v > N1) { N2 = N1; N1 = v; J1 = i; }
                        else if (v > N2) N2 = v;
                    }
                }
#pragma unroll
                for (int off = 4; off <= 16; off <<= 1) {
                    const float q1 = __shfl_xor_sync(~0u, P1, off);
                    const float q2 = __shfl_xor_sync(~0u, P2, off);
                    const int   qi = __shfl_xor_sync(~0u, I1, off);
                    const float m1 = __shfl_xor_sync(~0u, N1, off);
                    const float m2 = __shfl_xor_sync(~0u, N2, off);
                    const int   mi = __shfl_xor_sync(~0u, J1, off);
                    MERGE_MIN(P1, P2, I1, q1, q2, qi);
                    MERGE_MAX(N1, N2, J1, m1, m2, mi);
                }
                if ((L >> 2) == 0) {
                    const int col = wn * 32 + nt * 8 + (L & 3) * 2 + e;
                    float* sr = scr + (col * 4 + wm) * 8;
                    sr[0] = P1; sr[1] = P2;
                    reinterpret_cast<int*>(sr)[2] = I1;
                    sr[3] = N1; sr[4] = N2;
                    reinterpret_cast<int*>(sr)[5] = J1;
                }
            }
            __syncthreads();
            if (tid < 128) {
                const int col = tid;
                const float* s0 = scr + (col * 4) * 8;
                float P1 = s0[0], P2 = s0[1], N1 = s0[3], N2 = s0[4];
                int I1 = reinterpret_cast<const int*>(s0)[2];
                int J1 = reinterpret_cast<const int*>(s0)[5];
#pragma unroll
                for (int o = 1; o < 4; ++o) {
                    const float* sr = scr + (col * 4 + o) * 8;
                    MERGE_MIN(P1, P2, I1, sr[0], sr[1], reinterpret_cast<const int*>(sr)[2]);
                    MERGE_MAX(N1, N2, J1, sr[3], sr[4], reinterpret_cast<const int*>(sr)[5]);
                }
                float4* dst = reinterpret_cast<float4*>(
                    g_part + ((size_t)(d * NB + jt * BM + col) * 64 + it) * 8);
                dst[0] = make_float4(P1, P2, __int_as_float(I1), N1);
                dst[1] = make_float4(N2, __int_as_float(J1), 0.f, 0.f);
            }
        }
        __syncthreads();

        // A reload for next pair (if row-tile changes)
        if (q + 1 < CHUNK && itq[q + 1] != it) {
            copy_tile_async(sb + OFF_AH, sb + OFF_AL,
                            gh + (size_t)itq[q + 1] * BM * NF,
                            gl + (size_t)itq[q + 1] * BM * NF, tid);
            const uint32_t bo = OFF_B + (uint32_t)((q + 1) & 1) * 65536u;
            copy_tile_async(sb + bo, sb + bo + 32768u,
                            gh + (size_t)jtq[q + 1] * BM * NF,
                            gl + (size_t)jtq[q + 1] * BM * NF, tid);
            CP_COMMIT();
#pragma unroll
            for (int s = 0; s < 4; ++s)
                li[s] = labd[itq[q + 1] * BM + rbase + (s & 1) * 8 + (s >> 1) * 16];
        }
    }
}

// ---------------- merge 64 partials per row, write outputs, flag margins ----------------
__global__ void merge_kernel(const float* __restrict__ emb,
                             float* __restrict__ pos_dist,
                             float* __restrict__ neg_dist,
                             float* __restrict__ pos_embed,
                             float* __restrict__ neg_embed) {
    const int gw = (blockIdx.x * blockDim.x + threadIdx.x) >> 5;  // global row id
    const int L = threadIdx.x & 31;
    const float INF = __int_as_float(0x7f800000);

    const float4* bp = reinterpret_cast<const float4*>(g_part + (size_t)gw * 512);
    const float4 a0 = bp[L * 2],        b0 = bp[L * 2 + 1];
    const float4 a1 = bp[(L + 32) * 2], b1 = bp[(L + 32) * 2 + 1];

    float P1 = a0.x, P2 = a0.y, N1 = a0.w, N2 = b0.x;
    int I1 = __float_as_int(a0.z), J1 = __float_as_int(b0.y);
    MERGE_MIN(P1, P2, I1, a1.x, a1.y, __float_as_int(a1.z));
    MERGE_MAX(N1, N2, J1, a1.w, b1.x, __float_as_int(b1.y));
#pragma unroll
    for (int off = 1; off <= 16; off <<= 1) {
        const float q1 = __shfl_xor_sync(~0u, P1, off);
        const float q2 = __shfl_xor_sync(~0u, P2, off);
        const int   qi = __shfl_xor_sync(~0u, I1, off);
        const float m1 = __shfl_xor_sync(~0u, N1, off);
        const float m2 = __shfl_xor_sync(~0u, N2, off);
        const int   mi = __shfl_xor_sync(~0u, J1, off);
        MERGE_MIN(P1, P2, I1, q1, q2, qi);
        MERGE_MAX(N1, N2, J1, m1, m2, mi);
    }

    const bool has_pos = (P1 < INF);
    const int d = gw >> 13;
    if (L == 0) {
        pos_dist[gw] = has_pos ? P1 : 0.0f;
        neg_dist[gw] = has_pos ? N1 : 0.0f;
        if (has_pos) {
            const int basec = gw << 1;
            if (P2 - P1 < MARGIN) {
                const int x = atomicAdd(&g_flag_cnt, 1);
                if (x < MAXFLAGS) g_flags[x] = basec | 0;
            }
            if (N1 - N2 < MARGIN) {
                const int x = atomicAdd(&g_flag_cnt, 1);
                if (x < MAXFLAGS) g_flags[x] = basec | 1;
            }
        }
    }
    float4* pdst = reinterpret_cast<float4*>(pos_embed + (size_t)gw * NF);
    float4* ndst = reinterpret_cast<float4*>(neg_embed + (size_t)gw * NF);
    if (has_pos) {
        pdst[L] = reinterpret_cast<const float4*>(emb + ((size_t)d * NB + I1) * NF)[L];
        ndst[L] = reinterpret_cast<const float4*>(emb + ((size_t)d * NB + J1) * NF)[L];
    } else {
        const float4 z = make_float4(0.f, 0.f, 0.f, 0.f);
        pdst[L] = z; ndst[L] = z;
    }
}

// ---------------- exact refine (persistent small grids) ----------------
__global__ void refine_scan_kernel(const float* __restrict__ emb) {
    __shared__ float srow[NF];
    __shared__ int sli;
    __shared__ unsigned long long swb[8];
    const int cnt = min(g_flag_cnt, MAXFLAGS);
    for (int f = blockIdx.x; f < cnt; f += gridDim.x) {
        const int code = g_flags[f];
        const int side = code & 1, gr = code >> 1;
        const int d = gr >> 13, row = gr & (NB - 1);
        const float* __restrict__ embd = emb + (size_t)d * NB * NF;
        __syncthreads();
        if (threadIdx.x < NF) srow[threadIdx.x] = embd[(size_t)row * NF + threadIdx.x];
        if (threadIdx.x == 0) sli = g_labels[d * NB + row];
        __syncthreads();
        const int li = sli;
        const float4* a4 = reinterpret_cast<const float4*>(srow);

        unsigned long long best = 0ull;
        for (int j = threadIdx.x; j < NB; j += blockDim.x) {
            const int lj = g_labels[d * NB + j];
            const bool valid = side ? (lj != li) : (lj == li && j != row);
            if (!valid) continue;
            const float4* b4 = reinterpret_cast<const float4*>(embd + (size_t)j * NF);
            float accv = 0.0f;
#pragma unroll
            for (int qq = 0; qq < 32; ++qq) {
                const float4 av = a4[qq], bv = b4[qq];
                accv = fmaf(av.x, bv.x, accv);
                accv = fmaf(av.y, bv.y, accv);
                accv = fmaf(av.z, bv.z, accv);
                accv = fmaf(av.w, bv.w, accv);
            }
            uint32_t key = fkey(accv);
            if (!side) key = ~key;
            const unsigned long long pk =
                ((unsigned long long)key << 32) | (uint32_t)(NB - 1 - j);
            if (pk > best) best = pk;
        }
#pragma unroll
        for (int off = 16; off > 0; off >>= 1) {
            const unsigned long long o = __shfl_xor_sync(~0u, best, off);
            if (o > best) best = o;
        }
        if ((threadIdx.x & 31) == 0) swb[threadIdx.x >> 5] = best;
        __syncthreads();
        if (threadIdx.x == 0) {
            unsigned long long b = swb[0];
#pragma unroll
            for (int o = 1; o < 8; ++o) if (swb[o] > b) b = swb[o];
            g_best[f] = b;
        }
    }
}

__global__ void refine_write_kernel(const float* __restrict__ emb,
                                    float* __restrict__ pos_dist,
                                    float* __restrict__ neg_dist,
                                    float* __restrict__ pos_embed,
                                    float* __restrict__ neg_embed) {
    const int cnt = min(g_flag_cnt, MAXFLAGS);
    for (int f = blockIdx.x; f < cnt; f += gridDim.x) {
        const int code = g_flags[f];
        const int side = code & 1, gr = code >> 1;
        const int d = gr >> 13, row = gr & (NB - 1);
        const unsigned long long pk = g_best[f];
        const uint32_t key = (uint32_t)(pk >> 32);
        const int j = NB - 1 - (int)(pk & 0xFFFFFFFFull);
        const uint32_t m = side ? key : ~key;
        const uint32_t u = (m & 0x80000000u) ? (m & 0x7FFFFFFFu) : ~m;
        const float v = __uint_as_float(u);

        const size_t go = (size_t)d * NB + row;
        float* dist = side ? neg_dist : pos_dist;
        float* embo = side ? neg_embed : pos_embed;
        if (threadIdx.x == 0) dist[go] = v;
        embo[go * NF + threadIdx.x] = emb[((size_t)d * NB + j) * NF + threadIdx.x];
    }
}

// ---------------- launch ----------------
extern "C" void kernel_launch(void* const* d_in, const int* in_sizes, int n_in,
                              void* d_out, int out_size) {
    (void)in_sizes; (void)n_in; (void)out_size;
    const float* emb = (const float*)d_in[0];
    const unsigned int* labw = (const unsigned int*)d_in[1];

    float* out = (float*)d_out;
    float* pos_dist  = out;
    float* neg_dist  = out + (size_t)NDOM * NB;
    float* pos_embed = out + (size_t)2 * NDOM * NB;
    float* neg_embed = pos_embed + (size_t)NDOM * NB * NF;

    convert_labels_kernel<<<1, 256>>>(labw, NDOM * NB);
    split_kernel<<<(NDOM * NB * NF / 4) / 256, 256>>>(emb);

    cudaFuncSetAttribute(mine_kernel,
                         cudaFuncAttributeMaxDynamicSharedMemorySize, SMEM_BYTES);
    dim3 grid(NCTA_X, NDOM);
    mine_kernel<<<grid, NTHREADS, SMEM_BYTES>>>();

    merge_kernel<<<(NDOM * NB * 32) / 256, 256>>>(emb, pos_dist, neg_dist,
                                                  pos_embed, neg_embed);
    refine_scan_kernel<<<128, 256>>>(emb);
    refine_write_kernel<<<64, NF>>>(emb, pos_dist, neg_dist,
                                    pos_embed, neg_embed);
}

// round 8
// speedup vs baseline: 1.0089x; 1.0089x over previous
#include <cuda_runtime.h>
#include <cuda_fp16.h>
#include <cstdint>

#define NDOM 4
#define NB   8192
#define NF   128
#define BM   128
#define NTILE 64
#define NPAIRS 2080            /* NTILE*(NTILE+1)/2 */
#define CHUNK 4
#define NCTA_X (NPAIRS / CHUNK) /* 520 */
#define NTHREADS 512
#define MARGIN 2e-4f
#define MAXFLAGS 1024
#define SLOTS 256              /* 64 opp tiles x 4 warps */

// ---------------- SMEM layout (byte offsets) ----------------
#define OFF_AH  0u             /* A hi 32KB (swizzled row-major fp16) */
#define OFF_AL  32768u
#define OFF_B   65536u         /* buf b at OFF_B + b*65536: hi 32KB, lo +32768 */
#define SMEM_BYTES 196608u

__device__ int g_labels[NDOM * NB];
__device__ int g_flag_cnt;
__device__ int g_flags[MAXFLAGS];
__device__ unsigned long long g_best[MAXFLAGS];
__device__ __half g_hi[NDOM * NB * NF];
__device__ __half g_lo[NDOM * NB * NF];
// per-row partial top-2: [d*NB+row][slot 0..255][8 floats: p1,p2,i1,n1,n2,j1,pad,pad]
__device__ float g_part[(size_t)NDOM * NB * SLOTS * 8];   // 268MB

// ---------------- helpers ----------------
__device__ __forceinline__ uint32_t smem_u32(const void* p) {
    uint32_t a;
    asm("{ .reg .u64 t; cvta.to.shared.u64 t, %1; cvt.u32.u64 %0, t; }"
        : "=r"(a) : "l"(p));
    return a;
}
__device__ __forceinline__ uint32_t fkey(float v) {
    uint32_t u = __float_as_uint(v);
    return (u & 0x80000000u) ? ~u : (u | 0x80000000u);
}
__device__ __forceinline__ void ldsm4(uint32_t* r, uint32_t addr) {
    asm volatile("ldmatrix.sync.aligned.m8n8.x4.shared.b16 {%0,%1,%2,%3}, [%4];"
                 : "=r"(r[0]), "=r"(r[1]), "=r"(r[2]), "=r"(r[3]) : "r"(addr));
}
__device__ __forceinline__ void mma16816(float* d, const uint32_t* a,
                                         const uint32_t* b) {
    asm volatile(
        "mma.sync.aligned.m16n8k16.row.col.f32.f16.f16.f32 "
        "{%0,%1,%2,%3}, {%4,%5,%6,%7}, {%8,%9}, {%0,%1,%2,%3};"
        : "+f"(d[0]), "+f"(d[1]), "+f"(d[2]), "+f"(d[3])
        : "r"(a[0]), "r"(a[1]), "r"(a[2]), "r"(a[3]), "r"(b[0]), "r"(b[1]));
}
#define CP_ASYNC(dst, src) \
    asm volatile("cp.async.cg.shared.global [%0], [%1], 16;" :: "r"(dst), "l"(src))
#define CP_COMMIT() asm volatile("cp.async.commit_group;" ::: "memory")
#define CP_WAIT1()  asm volatile("cp.async.wait_group 1;" ::: "memory")
#define CP_WAIT0()  asm volatile("cp.async.wait_group 0;" ::: "memory")

__device__ __forceinline__ void copy_tile_async(
    uint32_t smem_hi, uint32_t smem_lo,
    const __half* __restrict__ gh, const __half* __restrict__ gl, int tid) {
#pragma unroll
    for (int it = 0; it < 8; ++it) {
        const int comp = it >> 2;
        const int rem = (it & 3) * NTHREADS + tid;   // 0..2047
        const int row = rem >> 4;
        const int kc = rem & 15;
        const uint32_t dstb = (uint32_t)row * 256u
            + (((uint32_t)kc * 16u) ^ (((uint32_t)row & 7u) << 4));
        const __half* src = (comp ? gl : gh) + row * NF + kc * 8;
        CP_ASYNC((comp ? smem_lo : smem_hi) + dstb, src);
    }
}

#define MERGE_MIN(P1, P2, I1, q1, q2, qi) \
    do { if ((q1) < (P1)) { P2 = fminf(P1, q2); P1 = q1; I1 = qi; } \
         else { P2 = fminf(P2, q1); } } while (0)
#define MERGE_MAX(N1, N2, J1, m1, m2, mi) \
    do { if ((m1) > (N1)) { N2 = fmaxf(N1, m2); N1 = m1; J1 = mi; } \
         else { N2 = fmaxf(N2, m1); } } while (0)

// ---------------- one-shot fp32 -> fp16 hi/lo split ----------------
__global__ void split_kernel(const float* __restrict__ emb) {
    const int i = blockIdx.x * blockDim.x + threadIdx.x;
    const float4 v = reinterpret_cast<const float4*>(emb)[i];
    const __half hx = __float2half_rn(v.x), hy = __float2half_rn(v.y);
    const __half hz = __float2half_rn(v.z), hw = __float2half_rn(v.w);
    const __half lx = __float2half_rn(v.x - __half2float(hx));
    const __half ly = __float2half_rn(v.y - __half2float(hy));
    const __half lz = __float2half_rn(v.z - __half2float(hz));
    const __half lw = __float2half_rn(v.w - __half2float(hw));
    uint2 hv, lv;
    hv.x = ((uint32_t)__half_as_ushort(hx)) | ((uint32_t)__half_as_ushort(hy) << 16);
    hv.y = ((uint32_t)__half_as_ushort(hz)) | ((uint32_t)__half_as_ushort(hw) << 16);
    lv.x = ((uint32_t)__half_as_ushort(lx)) | ((uint32_t)__half_as_ushort(ly) << 16);
    lv.y = ((uint32_t)__half_as_ushort(lz)) | ((uint32_t)__half_as_ushort(lw) << 16);
    reinterpret_cast<uint2*>(g_hi)[i] = hv;
    reinterpret_cast<uint2*>(g_lo)[i] = lv;
}

// ---------------- label normalization + flag reset ----------------
__global__ void convert_labels_kernel(const unsigned int* __restrict__ w, int n) {
    __shared__ int s_any;
    if (threadIdx.x == 0) { s_any = 0; g_flag_cnt = 0; }
    __syncthreads();
    int any = 0;
    for (int i = threadIdx.x; i < n / 2; i += blockDim.x)
        any |= (w[2 * i + 1] != 0u);
    if (any) atomicOr(&s_any, 1);
    for (int i = threadIdx.x; i < MAXFLAGS; i += blockDim.x) g_best[i] = 0ull;
    __syncthreads();
    const bool is64 = (s_any == 0);
    for (int i = threadIdx.x; i < n; i += blockDim.x)
        g_labels[i] = is64 ? (int)w[2 * i] : (int)w[i];
}

// ---------------- symmetric fused HMMA GEMM, barrier-free mining ----------------
__global__ __launch_bounds__(NTHREADS, 1)
void mine_kernel() {
    extern __shared__ char smem[];
    const uint32_t sb = smem_u32(smem);
    const int tid = threadIdx.x;
    const int w = tid >> 5, L = tid & 31;
    const int wm = w & 3, wn = w >> 2;
    const int d = blockIdx.y;

    int itq[CHUNK], jtq[CHUNK];
    {
        int it = 0, pp = blockIdx.x * CHUNK;
        while (pp >= NTILE - it) { pp -= NTILE - it; ++it; }
        int jt = it + pp;
#pragma unroll
        for (int q = 0; q < CHUNK; ++q) {
            itq[q] = it; jtq[q] = jt;
            if (++jt == NTILE) { ++it; jt = it; }
        }
    }

    const __half* __restrict__ gh = g_hi + (size_t)d * NB * NF;
    const __half* __restrict__ gl = g_lo + (size_t)d * NB * NF;
    const int* __restrict__ labd = g_labels + d * NB;

    // prologue: A(it0) + B(jt0)
    copy_tile_async(sb + OFF_AH, sb + OFF_AL,
                    gh + (size_t)itq[0] * BM * NF, gl + (size_t)itq[0] * BM * NF, tid);
    copy_tile_async(sb + OFF_B, sb + OFF_B + 32768u,
                    gh + (size_t)jtq[0] * BM * NF, gl + (size_t)jtq[0] * BM * NF, tid);
    CP_COMMIT();

    const uint32_t cxA = ((uint32_t)(L >> 4) * 16u) ^ (((uint32_t)L & 7u) << 4);
    const uint32_t cxB = ((uint32_t)((L >> 3) & 1) * 16u) ^ (((uint32_t)L & 7u) << 4);
    uint32_t aBase[2];
#pragma unroll
    for (int mt = 0; mt < 2; ++mt) {
        const int rowA = wm * 32 + mt * 16 + (L & 7) + ((L >> 3) & 1) * 8;
        aBase[mt] = sb + OFF_AH + (uint32_t)rowA * 256u;
    }
    uint32_t bRow[2];
#pragma unroll
    for (int bi = 0; bi < 2; ++bi) {
        const int rowB = wn * 32 + bi * 16 + (L & 7) + (L >> 4) * 8;
        bRow[bi] = (uint32_t)rowB * 256u;
    }

    const int rbase = wm * 32 + (L >> 2);
    int li[4];
#pragma unroll
    for (int s = 0; s < 4; ++s)
        li[s] = labd[itq[0] * BM + rbase + (s & 1) * 8 + (s >> 1) * 16];

    const float INF = __int_as_float(0x7f800000);

#pragma unroll
    for (int q = 0; q < CHUNK; ++q) {
        const int it = itq[q], jt = jtq[q];

        // (1) all warps done reading prior buffers -> safe to overwrite
        __syncthreads();
        if (q + 1 < CHUNK && itq[q + 1] == it) {
            const uint32_t bo = OFF_B + (uint32_t)((q + 1) & 1) * 65536u;
            copy_tile_async(sb + bo, sb + bo + 32768u,
                            gh + (size_t)jtq[q + 1] * BM * NF,
                            gl + (size_t)jtq[q + 1] * BM * NF, tid);
            CP_COMMIT();
            CP_WAIT1();
        } else {
            CP_WAIT0();
        }
        // (2) tile q's data visible to all threads
        __syncthreads();

        // column labels
        const int cb = jt * BM + wn * 32 + (L & 3) * 2;
        int labc[4][2];
#pragma unroll
        for (int nt = 0; nt < 4; ++nt) {
            const int2 lv = *reinterpret_cast<const int2*>(labd + cb + nt * 8);
            labc[nt][0] = lv.x; labc[nt][1] = lv.y;
        }

        // ---- MMA (3-pass fp16 hi/lo) ----
        float acc[2][4][4];
#pragma unroll
        for (int mt = 0; mt < 2; ++mt)
#pragma unroll
            for (int nt = 0; nt < 4; ++nt)
#pragma unroll
                for (int r = 0; r < 4; ++r) acc[mt][nt][r] = 0.0f;

        const uint32_t sbB = sb + OFF_B + (uint32_t)(q & 1) * 65536u;
#pragma unroll
        for (int ks = 0; ks < 8; ++ks) {
            const uint32_t offA = ((uint32_t)ks * 32u) ^ cxA;
            const uint32_t offB = ((uint32_t)ks * 32u) ^ cxB;
            uint32_t Ah[2][4], Al[2][4], Bh[2][4], Bl[2][4];
            ldsm4(Ah[0], aBase[0] + offA);
            ldsm4(Ah[1], aBase[1] + offA);
            ldsm4(Bh[0], sbB + bRow[0] + offB);
            ldsm4(Bh[1], sbB + bRow[1] + offB);
            ldsm4(Al[0], aBase[0] + 32768u + offA);
            ldsm4(Al[1], aBase[1] + 32768u + offA);
            ldsm4(Bl[0], sbB + 32768u + bRow[0] + offB);
            ldsm4(Bl[1], sbB + 32768u + bRow[1] + offB);
#pragma unroll
            for (int bi = 0; bi < 2; ++bi)
#pragma unroll
                for (int mt = 0; mt < 2; ++mt) {
                    mma16816(acc[mt][2 * bi],     Ah[mt], Bh[bi]);
                    mma16816(acc[mt][2 * bi + 1], Ah[mt], Bh[bi] + 2);
                }
#pragma unroll
            for (int bi = 0; bi < 2; ++bi)
#pragma unroll
                for (int mt = 0; mt < 2; ++mt) {
                    mma16816(acc[mt][2 * bi],     Al[mt], Bh[bi]);
                    mma16816(acc[mt][2 * bi + 1], Al[mt], Bh[bi] + 2);
                }
#pragma unroll
            for (int bi = 0; bi < 2; ++bi)
#pragma unroll
                for (int mt = 0; mt < 2; ++mt) {
                    mma16816(acc[mt][2 * bi],     Ah[mt], Bl[bi]);
                    mma16816(acc[mt][2 * bi + 1], Ah[mt], Bl[bi] + 2);
                }
        }

        // ---- row-side mining: per-warp top-2 over 32 cols -> global slot ----
        {
            float p1[4], p2[4], n1[4], n2[4];
            int i1[4], j1[4];
#pragma unroll
            for (int s = 0; s < 4; ++s) {
                p1[s] = INF; p2[s] = INF; n1[s] = -INF; n2[s] = -INF;
                i1[s] = -1; j1[s] = -1;
            }
#pragma unroll
            for (int nt = 0; nt < 4; ++nt)
#pragma unroll
                for (int e = 0; e < 2; ++e) {
                    const int lj = labc[nt][e];
                    const int j = cb + nt * 8 + e;
#pragma unroll
                    for (int s = 0; s < 4; ++s) {
                        const float v = acc[s >> 1][nt][(s & 1) * 2 + e];
                        if (lj == li[s]) {
                            const int growl = it * BM + rbase + (s & 1) * 8 + (s >> 1) * 16;
                            if (j != growl) {
                                if (v < p1[s]) { p2[s] = p1[s]; p1[s] = v; i1[s] = j; }
                                else if (v < p2[s]) p2[s] = v;
                            }
                        } else {
                            if (v > n1[s]) { n2[s] = n1[s]; n1[s] = v; j1[s] = j; }
                            else if (v > n2[s]) n2[s] = v;
                        }
                    }
                }
#pragma unroll
            for (int s = 0; s < 4; ++s) {
#pragma unroll
                for (int off = 1; off <= 2; off <<= 1) {
                    const float q1 = __shfl_xor_sync(~0u, p1[s], off);
                    const float q2 = __shfl_xor_sync(~0u, p2[s], off);
                    const int   qi = __shfl_xor_sync(~0u, i1[s], off);
                    const float m1 = __shfl_xor_sync(~0u, n1[s], off);
                    const float m2 = __shfl_xor_sync(~0u, n2[s], off);
                    const int   mi = __shfl_xor_sync(~0u, j1[s], off);
                    MERGE_MIN(p1[s], p2[s], i1[s], q1, q2, qi);
                    MERGE_MAX(n1[s], n2[s], j1[s], m1, m2, mi);
                }
            }
            if ((L & 3) == 0) {
#pragma unroll
                for (int s = 0; s < 4; ++s) {
                    const int row = it * BM + rbase + (s & 1) * 8 + (s >> 1) * 16;
                    float4* dst = reinterpret_cast<float4*>(
                        g_part + ((size_t)(d * NB + row) * SLOTS + jt * 4 + wn) * 8);
                    dst[0] = make_float4(p1[s], p2[s], __int_as_float(i1[s]), n1[s]);
                    dst[1] = make_float4(n2[s], __int_as_float(j1[s]), 0.f, 0.f);
                }
            }
        }

        // ---- column-side mining via symmetry (skip diagonal) ----
        if (it != jt) {
#pragma unroll
            for (int c = 0; c < 8; ++c) {
                const int nt = c >> 1, e = c & 1;
                const int lj = labc[nt][e];
                float P1 = INF, P2 = INF, N1 = -INF, N2 = -INF;
                int I1 = -1, J1 = -1;
#pragma unroll
                for (int s = 0; s < 4; ++s) {
                    const float v = acc[s >> 1][nt][(s & 1) * 2 + e];
                    const int i = it * BM + rbase + (s & 1) * 8 + (s >> 1) * 16;
                    if (li[s] == lj) {
                        if (v < P1) { P2 = P1; P1 = v; I1 = i; }
                        else if (v < P2) P2 = v;
                    } else {
                        if (v > N1) { N2 = N1; N1 = v; J1 = i; }
                        else if (v > N2) N2 = v;
                    }
                }
#pragma unroll
                for (int off = 4; off <= 16; off <<= 1) {
                    const float q1 = __shfl_xor_sync(~0u, P1, off);
                    const float q2 = __shfl_xor_sync(~0u, P2, off);
                    const int   qi = __shfl_xor_sync(~0u, I1, off);
                    const float m1 = __shfl_xor_sync(~0u, N1, off);
                    const float m2 = __shfl_xor_sync(~0u, N2, off);
                    const int   mi = __shfl_xor_sync(~0u, J1, off);
                    MERGE_MIN(P1, P2, I1, q1, q2, qi);
                    MERGE_MAX(N1, N2, J1, m1, m2, mi);
                }
                if (L < 4) {
                    const int col = jt * BM + wn * 32 + nt * 8 + L * 2 + e;
                    float4* dst = reinterpret_cast<float4*>(
                        g_part + ((size_t)(d * NB + col) * SLOTS + it * 4 + wm) * 8);
                    dst[0] = make_float4(P1, P2, __int_as_float(I1), N1);
                    dst[1] = make_float4(N2, __int_as_float(J1), 0.f, 0.f);
                }
            }
        } else {
            // diagonal: column-side == row-side; write the other wn-slot range
            // is unnecessary — rows of it already covered by row-side slots.
        }

        // A/B reload when the row tile changes
        if (q + 1 < CHUNK && itq[q + 1] != it) {
            __syncthreads();   // all warps done with A + current B
            copy_tile_async(sb + OFF_AH, sb + OFF_AL,
                            gh + (size_t)itq[q + 1] * BM * NF,
                            gl + (size_t)itq[q + 1] * BM * NF, tid);
            const uint32_t bo = OFF_B + (uint32_t)((q + 1) & 1) * 65536u;
            copy_tile_async(sb + bo, sb + bo + 32768u,
                            gh + (size_t)jtq[q + 1] * BM * NF,
                            gl + (size_t)jtq[q + 1] * BM * NF, tid);
            CP_COMMIT();
#pragma unroll
            for (int s = 0; s < 4; ++s)
                li[s] = labd[itq[q + 1] * BM + rbase + (s & 1) * 8 + (s >> 1) * 16];
        }
    }
}

// ---------------- merge 256 partials per row, write outputs, flag margins ----------------
__global__ void merge_kernel(const float* __restrict__ emb,
                             float* __restrict__ pos_dist,
                             float* __restrict__ neg_dist,
                             float* __restrict__ pos_embed,
                             float* __restrict__ neg_embed) {
    const int gw = (blockIdx.x * blockDim.x + threadIdx.x) >> 5;  // global row id
    const int L = threadIdx.x & 31;
    const float INF = __int_as_float(0x7f800000);

    const float4* bp = reinterpret_cast<const float4*>(g_part + (size_t)gw * SLOTS * 8);
    float4 a = bp[L * 2], b = bp[L * 2 + 1];
    float P1 = a.x, P2 = a.y, N1 = a.w, N2 = b.x;
    int I1 = __float_as_int(a.z), J1 = __float_as_int(b.y);
#pragma unroll
    for (int s = 1; s < 8; ++s) {
        a = bp[(L + s * 32) * 2]; b = bp[(L + s * 32) * 2 + 1];
        MERGE_MIN(P1, P2, I1, a.x, a.y, __float_as_int(a.z));
        MERGE_MAX(N1, N2, J1, a.w, b.x, __float_as_int(b.y));
    }
#pragma unroll
    for (int off = 1; off <= 16; off <<= 1) {
        const float q1 = __shfl_xor_sync(~0u, P1, off);
        const float q2 = __shfl_xor_sync(~0u, P2, off);
        const int   qi = __shfl_xor_sync(~0u, I1, off);
        const float m1 = __shfl_xor_sync(~0u, N1, off);
        const float m2 = __shfl_xor_sync(~0u, N2, off);
        const int   mi = __shfl_xor_sync(~0u, J1, off);
        MERGE_MIN(P1, P2, I1, q1, q2, qi);
        MERGE_MAX(N1, N2, J1, m1, m2, mi);
    }

    const bool has_pos = (P1 < INF);
    const int d = gw >> 13;
    if (L == 0) {
        pos_dist[gw] = has_pos ? P1 : 0.0f;
        neg_dist[gw] = has_pos ? N1 : 0.0f;
        if (has_pos) {
            const int basec = gw << 1;
            if (P2 - P1 < MARGIN) {
                const int x = atomicAdd(&g_flag_cnt, 1);
                if (x < MAXFLAGS) g_flags[x] = basec | 0;
            }
            if (N1 - N2 < MARGIN) {
                const int x = atomicAdd(&g_flag_cnt, 1);
                if (x < MAXFLAGS) g_flags[x] = basec | 1;
            }
        }
    }
    float4* pdst = reinterpret_cast<float4*>(pos_embed + (size_t)gw * NF);
    float4* ndst = reinterpret_cast<float4*>(neg_embed + (size_t)gw * NF);
    if (has_pos) {
        pdst[L] = reinterpret_cast<const float4*>(emb + ((size_t)d * NB + I1) * NF)[L];
        ndst[L] = reinterpret_cast<const float4*>(emb + ((size_t)d * NB + J1) * NF)[L];
    } else {
        const float4 z = make_float4(0.f, 0.f, 0.f, 0.f);
        pdst[L] = z; ndst[L] = z;
    }
}

// ---------------- exact refine (persistent small grids) ----------------
__global__ void refine_scan_kernel(const float* __restrict__ emb) {
    __shared__ float srow[NF];
    __shared__ int sli;
    __shared__ unsigned long long swb[8];
    const int cnt = min(g_flag_cnt, MAXFLAGS);
    for (int f = blockIdx.x; f < cnt; f += gridDim.x) {
        const int code = g_flags[f];
        const int side = code & 1, gr = code >> 1;
        const int d = gr >> 13, row = gr & (NB - 1);
        const float* __restrict__ embd = emb + (size_t)d * NB * NF;
        __syncthreads();
        if (threadIdx.x < NF) srow[threadIdx.x] = embd[(size_t)row * NF + threadIdx.x];
        if (threadIdx.x == 0) sli = g_labels[d * NB + row];
        __syncthreads();
        const int li = sli;
        const float4* a4 = reinterpret_cast<const float4*>(srow);

        unsigned long long best = 0ull;
        for (int j = threadIdx.x; j < NB; j += blockDim.x) {
            const int lj = g_labels[d * NB + j];
            const bool valid = side ? (lj != li) : (lj == li && j != row);
            if (!valid) continue;
            const float4* b4 = reinterpret_cast<const float4*>(embd + (size_t)j * NF);
            float accv = 0.0f;
#pragma unroll
            for (int qq = 0; qq < 32; ++qq) {
                const float4 av = a4[qq], bv = b4[qq];
                accv = fmaf(av.x, bv.x, accv);
                accv = fmaf(av.y, bv.y, accv);
                accv = fmaf(av.z, bv.z, accv);
                accv = fmaf(av.w, bv.w, accv);
            }
            uint32_t key = fkey(accv);
            if (!side) key = ~key;
            const unsigned long long pk =
                ((unsigned long long)key << 32) | (uint32_t)(NB - 1 - j);
            if (pk > best) best = pk;
        }
#pragma unroll
        for (int off = 16; off > 0; off >>= 1) {
            const unsigned long long o = __shfl_xor_sync(~0u, best, off);
            if (o > best) best = o;
        }
        if ((threadIdx.x & 31) == 0) swb[threadIdx.x >> 5] = best;
        __syncthreads();
        if (threadIdx.x == 0) {
            unsigned long long b = swb[0];
#pragma unroll
            for (int o = 1; o < 8; ++o) if (swb[o] > b) b = swb[o];
            g_best[f] = b;
        }
    }
}

__global__ void refine_write_kernel(const float* __restrict__ emb,
                                    float* __restrict__ pos_dist,
                                    float* __restrict__ neg_dist,
                                    float* __restrict__ pos_embed,
                                    float* __restrict__ neg_embed) {
    const int cnt = min(g_flag_cnt, MAXFLAGS);
    for (int f = blockIdx.x; f < cnt; f += gridDim.x) {
        const int code = g_flags[f];
        const int side = code & 1, gr = code >> 1;
        const int d = gr >> 13, row = gr & (NB - 1);
        const unsigned long long pk = g_best[f];
        const uint32_t key = (uint32_t)(pk >> 32);
        const int j = NB - 1 - (int)(pk & 0xFFFFFFFFull);
        const uint32_t m = side ? key : ~key;
        const uint32_t u = (m & 0x80000000u) ? (m & 0x7FFFFFFFu) : ~m;
        const float v = __uint_as_float(u);

        const size_t go = (size_t)d * NB + row;
        float* dist = side ? neg_dist : pos_dist;
        float* embo = side ? neg_embed : pos_embed;
        if (threadIdx.x == 0) dist[go] = v;
        embo[go * NF + threadIdx.x] = emb[((size_t)d * NB + j) * NF + threadIdx.x];
    }
}

// ---------------- launch ----------------
extern "C" void kernel_launch(void* const* d_in, const int* in_sizes, int n_in,
                              void* d_out, int out_size) {
    (void)in_sizes; (void)n_in; (void)out_size;
    const float* emb = (const float*)d_in[0];
    const unsigned int* labw = (const unsigned int*)d_in[1];

    float* out = (float*)d_out;
    float* pos_dist  = out;
    float* neg_dist  = out + (size_t)NDOM * NB;
    float* pos_embed = out + (size_t)2 * NDOM * NB;
    float* neg_embed = pos_embed + (size_t)NDOM * NB * NF;

    convert_labels_kernel<<<1, 256>>>(labw, NDOM * NB);
    split_kernel<<<(NDOM * NB * NF / 4) / 256, 256>>>(emb);

    cudaFuncSetAttribute(mine_kernel,
                         cudaFuncAttributeMaxDynamicSharedMemorySize, SMEM_BYTES);
    dim3 grid(NCTA_X, NDOM);
    mine_kernel<<<grid, NTHREADS, SMEM_BYTES>>>();

    merge_kernel<<<(NDOM * NB * 32) / 256, 256>>>(emb, pos_dist, neg_dist,
                                                  pos_embed, neg_embed);
    refine_scan_kernel<<<128, 256>>>(emb);
    refine_write_kernel<<<64, NF>>>(emb, pos_dist, neg_dist,
                                    pos_embed, neg_embed);
}